// round 2
// baseline (speedup 1.0000x reference)
#include <cuda_runtime.h>
#include <cstdint>

// Problem constants
#define BATCH      256
#define TREES      64
#define FEAT       16080      // 120*134
#define MASK_W     1000
#define K_TOP      200
#define ROW_F4     (FEAT / 4)       // 4020
#define LIVE_F4    (MASK_W / 4)     // 250 (columns [0,1000) hold all nonzeros)

// ---------------------------------------------------------------------------
// Kernel 1: exact top-200 selection per tree + write attention row.
// One block per tree, 1024 threads. Rank by count-of-greater with jax's
// lower-index tie-break; select rank < 200. attention[t, i<1000] = selected ?
// sigmoid(v) : 0 ; attention[t, 1000:16080) = 0.
// ---------------------------------------------------------------------------
__global__ __launch_bounds__(1024)
void topk_attention_kernel(const float* __restrict__ mask, float* __restrict__ att_out)
{
    const int t   = blockIdx.x;
    const int tid = threadIdx.x;

    __shared__ float sv[MASK_W];

    if (tid < MASK_W) {
        sv[tid] = mask[t * MASK_W + tid];
    }
    __syncthreads();

    if (tid < MASK_W) {
        const float v = sv[tid];
        int rank = 0;
        #pragma unroll 8
        for (int j = 0; j < MASK_W; ++j) {
            const float u = sv[j];                       // smem broadcast
            rank += (u > v) || (u == v && j < tid);
        }
        float out = 0.0f;
        if (rank < K_TOP) {
            out = 1.0f / (1.0f + expf(-v));              // sigmoid
        }
        att_out[(size_t)t * FEAT + tid] = out;
    }

    // Zero-fill attention[t, 1000:16080)
    for (int f = MASK_W + tid; f < FEAT; f += 1024) {
        att_out[(size_t)t * FEAT + f] = 0.0f;
    }
}

// ---------------------------------------------------------------------------
// Kernel 2: return_value[b,t,f] = x[b,f] * attention[t,f].
// attention[t, f>=1000] == 0, so only the first 250 float4s per row need any
// input reads; the remaining 3770 float4s per row are pure zero stores.
// Store-bound: ~1.05 GB of STG.128.
// ---------------------------------------------------------------------------
__global__ __launch_bounds__(256)
void rv_kernel(const float* __restrict__ x,
               const float* __restrict__ att,
               float*       __restrict__ out)
{
    const int c4  = blockIdx.x * blockDim.x + threadIdx.x;   // float4 column
    if (c4 >= ROW_F4) return;
    const int row = blockIdx.y;                              // b*TREES + t
    const int t   = row & (TREES - 1);
    const int b   = row >> 6;

    float4* dst = reinterpret_cast<float4*>(out + (size_t)row * FEAT) + c4;

    float4 r;
    if (c4 < LIVE_F4) {
        const float4 xa = reinterpret_cast<const float4*>(x   + (size_t)b * FEAT)[c4];
        const float4 aa = reinterpret_cast<const float4*>(att + (size_t)t * FEAT)[c4];
        r.x = xa.x * aa.x;
        r.y = xa.y * aa.y;
        r.z = xa.z * aa.z;
        r.w = xa.w * aa.w;
    } else {
        r.x = 0.0f; r.y = 0.0f; r.z = 0.0f; r.w = 0.0f;
    }
    *dst = r;
}

// ---------------------------------------------------------------------------
// Launch
// ---------------------------------------------------------------------------
extern "C" void kernel_launch(void* const* d_in, const int* in_sizes, int n_in,
                              void* d_out, int out_size)
{
    const float* x    = (const float*)d_in[0];   // (256, 120, 134) fp32
    const float* mask = (const float*)d_in[1];   // (64, 1000) fp32

    float* out = (float*)d_out;
    float* rv_out  = out;                                           // (256, 64, 16080)
    float* att_out = out + (size_t)BATCH * TREES * FEAT;            // (64, 16080)

    // 1) top-k + attention row construction
    topk_attention_kernel<<<TREES, 1024>>>(mask, att_out);

    // 2) broadcast multiply (store-bound)
    dim3 grid((ROW_F4 + 255) / 256, BATCH * TREES);
    rv_kernel<<<grid, 256>>>(x, att_out, rv_out);
}

// round 3
// speedup vs baseline: 1.1535x; 1.1535x over previous
#include <cuda_runtime.h>
#include <cstdint>

// Problem constants
#define BATCH      256
#define TREES      64
#define FEAT       16080      // 120*134
#define MASK_W     1000
#define K_TOP      200
#define ROW_F4     (FEAT / 4)       // 4020
#define LIVE_F4    (MASK_W / 4)     // 250 (columns [0,1000) hold all nonzeros)

// ---------------------------------------------------------------------------
// Kernel 1: exact top-200 per tree via binary-search threshold selection.
// One block per tree, 256 threads.
//   - map floats to order-preserving uint32 keys
//   - binary search key domain for thr = 200th-largest key (<=32 iterations,
//     each a 4-compare/thread + block reduction)
//   - select key > thr, plus lowest-index equals to fill exactly 200
//     (exact jax lower-index tie-break; rank loop only on boundary ties)
// Writes attention[t, 0:1000] = selected ? sigmoid(v) : 0 and zeros the tail.
// ---------------------------------------------------------------------------
__global__ __launch_bounds__(256)
void topk_attention_kernel(const float* __restrict__ mask, float* __restrict__ att_out)
{
    const int t   = blockIdx.x;
    const int tid = threadIdx.x;

    __shared__ unsigned int skey[MASK_W];
    __shared__ float        sval[MASK_W];
    __shared__ int s_cnt, s_cgt, s_ceq;

    // Load + order-preserving transform (monotone: float order -> uint order)
    for (int i = tid; i < MASK_W; i += 256) {
        const float v = mask[t * MASK_W + i];
        sval[i] = v;
        const int s = __float_as_int(v);
        skey[i] = (s < 0) ? ~(unsigned int)s : ((unsigned int)s | 0x80000000u);
    }
    __syncthreads();

    // Cache this thread's keys in registers (sentinel 0 never matches:
    // search midpoints are >= 1 and real keys of finite floats are > 0)
    unsigned int k[4];
    #pragma unroll
    for (int q = 0; q < 4; ++q) {
        const int i = tid + q * 256;
        k[q] = (i < MASK_W) ? skey[i] : 0u;
    }

    // Binary search: thr = max T with count(key >= T) >= K_TOP  (== 200th largest)
    unsigned int lo = 0u, hi = 0xFFFFFFFFu;
    while (lo < hi) {
        const unsigned int mid = lo + ((hi - lo) >> 1) + 1u;   // upper mid, overflow-safe
        int c = 0;
        #pragma unroll
        for (int q = 0; q < 4; ++q) c += (k[q] >= mid);
        if (tid == 0) s_cnt = 0;
        __syncthreads();
        c = __reduce_add_sync(0xFFFFFFFFu, c);
        if ((tid & 31) == 0) atomicAdd(&s_cnt, c);
        __syncthreads();
        const int total = s_cnt;
        __syncthreads();                                        // protect reset next iter
        if (total >= K_TOP) lo = mid; else hi = mid - 1u;
    }
    const unsigned int thr = lo;

    // Count strictly-greater and equal-to-threshold
    if (tid == 0) { s_cgt = 0; s_ceq = 0; }
    __syncthreads();
    int cg = 0, ce = 0;
    #pragma unroll
    for (int q = 0; q < 4; ++q) { cg += (k[q] > thr); ce += (k[q] == thr); }
    cg = __reduce_add_sync(0xFFFFFFFFu, cg);
    ce = __reduce_add_sync(0xFFFFFFFFu, ce);
    if ((tid & 31) == 0) { atomicAdd(&s_cgt, cg); atomicAdd(&s_ceq, ce); }
    __syncthreads();
    const int need  = K_TOP - s_cgt;   // equals to accept (1 <= need <= eqtot)
    const int eqtot = s_ceq;

    // Write attention[t, 0:1000)
    #pragma unroll
    for (int q = 0; q < 4; ++q) {
        const int i = tid + q * 256;
        if (i < MASK_W) {
            bool sel = (k[q] > thr);
            if (k[q] == thr) {
                if (need >= eqtot) {
                    sel = true;                       // all equals fit (common case)
                } else {                              // boundary tie: lowest indices win
                    int r = 0;
                    for (int j = 0; j < i; ++j) r += (skey[j] == thr);
                    sel = (r < need);
                }
            }
            const float v = sval[i];
            att_out[(size_t)t * FEAT + i] = sel ? (1.0f / (1.0f + expf(-v))) : 0.0f;
        }
    }

    // Zero tail [1000, 16080) with float4 stores (1000 % 4 == 0)
    float4 z; z.x = 0.f; z.y = 0.f; z.z = 0.f; z.w = 0.f;
    float4* row4 = reinterpret_cast<float4*>(att_out + (size_t)t * FEAT);
    for (int f4 = LIVE_F4 + tid; f4 < ROW_F4; f4 += 256) {
        row4[f4] = z;
    }
}

// ---------------------------------------------------------------------------
// Kernel 2: return_value[b,t,f] = x[b,f] * attention[t,f].
// attention[t, f>=1000] == 0, so only the first 250 float4s per row read any
// input; the remaining 3770 float4s per row are pure zero stores.
// Streaming stores (evict-first) keep the hot x/att lines resident in L2.
// ---------------------------------------------------------------------------
__global__ __launch_bounds__(256)
void rv_kernel(const float* __restrict__ x,
               const float* __restrict__ att,
               float*       __restrict__ out)
{
    const int c4  = blockIdx.x * blockDim.x + threadIdx.x;   // float4 column
    if (c4 >= ROW_F4) return;
    const int row = blockIdx.y;                              // b*TREES + t
    const int t   = row & (TREES - 1);
    const int b   = row >> 6;

    float4* dst = reinterpret_cast<float4*>(out + (size_t)row * FEAT) + c4;

    float4 r;
    if (c4 < LIVE_F4) {
        const float4 xa = reinterpret_cast<const float4*>(x   + (size_t)b * FEAT)[c4];
        const float4 aa = reinterpret_cast<const float4*>(att + (size_t)t * FEAT)[c4];
        r.x = xa.x * aa.x;
        r.y = xa.y * aa.y;
        r.z = xa.z * aa.z;
        r.w = xa.w * aa.w;
    } else {
        r.x = 0.0f; r.y = 0.0f; r.z = 0.0f; r.w = 0.0f;
    }
    __stcs(dst, r);
}

// ---------------------------------------------------------------------------
// Launch
// ---------------------------------------------------------------------------
extern "C" void kernel_launch(void* const* d_in, const int* in_sizes, int n_in,
                              void* d_out, int out_size)
{
    const float* x    = (const float*)d_in[0];   // (256, 120, 134) fp32
    const float* mask = (const float*)d_in[1];   // (64, 1000) fp32

    float* out = (float*)d_out;
    float* rv_out  = out;                                           // (256, 64, 16080)
    float* att_out = out + (size_t)BATCH * TREES * FEAT;            // (64, 16080)

    // 1) top-k threshold selection + attention row construction
    topk_attention_kernel<<<TREES, 256>>>(mask, att_out);

    // 2) broadcast multiply (store-bound)
    dim3 grid((ROW_F4 + 255) / 256, BATCH * TREES);
    rv_kernel<<<grid, 256>>>(x, att_out, rv_out);
}